// round 16
// baseline (speedup 1.0000x reference)
#include <cuda_runtime.h>
#include <cstdint>

// FlowNetC correlation cost volume. Inputs [B=8, C=128, H=128, W=256] fp32.
// out[b, (dy+4)*9+(dx+4), y, x] = (1/128) * sum_c in1[b,c,y,x] * in2z[b,c,y+dy,x+dx]
// (in2z zero outside [0,H)x[0,W); PAD=4 >= max displacement 4.)
//
// R14: NO shared memory. Each thread owns 8 adjacent output cols and loads its
// 16-float b window directly with 4 LDG.128 (16B-aligned: window starts at col
// 8*lane-4). L1 serves lane overlap + cross-warp reuse:
//   block = 18 warps (576 thr) = 2 y-rows x 9 dy; the 9 dy-warps of a row share
//   one a row (1 L1 miss + 8 hits); the 18 b-row reads hit 12 distinct rows.
// Edge padding = 2 predicated loads (lane 0 first slot, lane 31 last slot).
// All-aligned f32x2 packing: even dx uses free b pairs bp[p+e]; odd dx pairs
// cols (1,2),(3,4),(5,6) vs ALIGNED bp[e+1..3] via 3 reusable a-packs;
// cols 0 and 7 scalar. 40 fma issues + 3 packs per channel per thread.

#define B_  8
#define C_  128
#define H_  128
#define W_  256
#define CHSTRIDE (H_ * W_)          // 32768 floats per channel plane

__device__ __forceinline__ unsigned long long pk2(float lo, float hi) {
    unsigned long long r;
    asm("mov.b64 %0, {%1, %2};" : "=l"(r) : "f"(lo), "f"(hi));
    return r;
}
__device__ __forceinline__ void fma2(unsigned long long& d,
                                     unsigned long long a, unsigned long long b) {
    asm("fma.rn.f32x2 %0, %1, %2, %0;" : "+l"(d) : "l"(a), "l"(b));
}
__device__ __forceinline__ float2 up2(unsigned long long v) {
    float2 r;
    asm("mov.b64 {%0, %1}, %2;" : "=f"(r.x), "=f"(r.y) : "l"(v));
    return r;
}

__global__ __launch_bounds__(576, 1)
void corr_kernel(const float* __restrict__ in1,
                 const float* __restrict__ in2,
                 float* __restrict__ out)
{
    const int y0   = (int)blockIdx.x * 2;
    const int b    = (int)blockIdx.y;
    const int wid  = (int)threadIdx.x >> 5;     // 0..17
    const int lane = (int)threadIdx.x & 31;
    const int y    = y0 + (wid >= 9);           // warps 0-8 -> y0, 9-17 -> y0+1
    const int dy   = (wid % 9) - 4;             // -4..4
    const int gy   = y + dy;
    const bool rowok = (unsigned)gy < (unsigned)H_;

    // a: 8 floats at cols 8*lane..8*lane+7 (always in-bounds).
    const float* ap = in1 + ((size_t)b * C_ * H_ + y) * W_ + (lane << 3);
    // b window: 16 floats at cols 8*lane-4 .. 8*lane+11; byte-16 aligned.
    const float* bp_ = in2 + ((size_t)b * C_ * H_ + (rowok ? gy : 0)) * W_
                           + (lane << 3) - 4;

    const bool p0 = rowok && (lane != 0);       // slot 0: cols 8l-4..8l-1
    const bool pm = rowok;                      // slots 1,2 always in-bounds rows
    const bool p3 = rowok && (lane != 31);      // slot 3: cols 8l+8..8l+11

    // Accumulators: 72 fp32. Even d=2e: 4 pairs (cols 01,23,45,67).
    // Odd d=2e+1: 3 pairs (cols 12,34,56) + scalars (cols 0,7).
    unsigned long long ae[5][4], am[4][3];
    float s0[4], s7[4];
#pragma unroll
    for (int e = 0; e < 5; ++e)
#pragma unroll
        for (int p = 0; p < 4; ++p) ae[e][p] = 0ull;
#pragma unroll
    for (int e = 0; e < 4; ++e) {
#pragma unroll
        for (int p = 0; p < 3; ++p) am[e][p] = 0ull;
        s0[e] = 0.0f; s7[e] = 0.0f;
    }

    const float4 z4 = make_float4(0.f, 0.f, 0.f, 0.f);

#pragma unroll 2
    for (int c = 0; c < C_; ++c) {
        const float* a = ap  + (size_t)c * CHSTRIDE;
        const float* w = bp_ + (size_t)c * CHSTRIDE;

        float4 a0 = *reinterpret_cast<const float4*>(a);
        float4 a1 = *reinterpret_cast<const float4*>(a + 4);
        float4 w0 = p0 ? *reinterpret_cast<const float4*>(w)      : z4;
        float4 w1 = pm ? *reinterpret_cast<const float4*>(w + 4)  : z4;
        float4 w2 = pm ? *reinterpret_cast<const float4*>(w + 8)  : z4;
        float4 w3 = p3 ? *reinterpret_cast<const float4*>(w + 12) : z4;

        // ww[i] <-> col 8*lane + i - 4; acc col i needs ww[i+d].
        float ww[16] = {w0.x, w0.y, w0.z, w0.w,  w1.x, w1.y, w1.z, w1.w,
                        w2.x, w2.y, w2.z, w2.w,  w3.x, w3.y, w3.z, w3.w};
        unsigned long long bp[8];                 // aligned halves: free pairs
#pragma unroll
        for (int k = 0; k < 8; ++k) bp[k] = pk2(ww[2 * k], ww[2 * k + 1]);

        unsigned long long A[4] = {pk2(a0.x, a0.y), pk2(a0.z, a0.w),
                                   pk2(a1.x, a1.y), pk2(a1.z, a1.w)};
        unsigned long long a12 = pk2(a0.y, a0.z);   // 3 unaligned packs,
        unsigned long long a34 = pk2(a0.w, a1.x);   // each reused 4x
        unsigned long long a56 = pk2(a1.y, a1.z);

        // even d = 2e: cols (2p,2p+1) += (a2p,a2p+1) * bp[p+e]
#pragma unroll
        for (int e = 0; e < 5; ++e)
#pragma unroll
            for (int p = 0; p < 4; ++p)
                fma2(ae[e][p], A[p], bp[p + e]);

        // odd d = 2e+1: cols (2p+1,2p+2) += (a..)*(ww[2p+2e+2],ww[2p+2e+3])
        //             = aligned bp[p+e+1]; cols 0,7 scalar.
#pragma unroll
        for (int e = 0; e < 4; ++e) {
            fma2(am[e][0], a12, bp[e + 1]);
            fma2(am[e][1], a34, bp[e + 2]);
            fma2(am[e][2], a56, bp[e + 3]);
            s0[e] = fmaf(a0.x, ww[2 * e + 1], s0[e]);   // col 0: ww[d]
            s7[e] = fmaf(a1.w, ww[2 * e + 8], s7[e]);   // col 7: ww[7+d]
        }
    }

    // ---- epilogue: scale by 1/C, two float4 stores per displacement ----
    const float sc = 1.0f / (float)C_;
    const size_t ob = (((size_t)b * 81 + (size_t)(dy + 4) * 9) * H_ + y) * W_
                    + (lane << 3);
#pragma unroll
    for (int e = 0; e < 5; ++e) {                 // d = 2e
        float2 q0 = up2(ae[e][0]), q1 = up2(ae[e][1]);
        float2 q2 = up2(ae[e][2]), q3 = up2(ae[e][3]);
        float4 v0 = make_float4(q0.x * sc, q0.y * sc, q1.x * sc, q1.y * sc);
        float4 v1 = make_float4(q2.x * sc, q2.y * sc, q3.x * sc, q3.y * sc);
        float* o = out + ob + (size_t)(2 * e) * H_ * W_;
        *reinterpret_cast<float4*>(o)     = v0;
        *reinterpret_cast<float4*>(o + 4) = v1;
    }
#pragma unroll
    for (int e = 0; e < 4; ++e) {                 // d = 2e+1
        float2 m0 = up2(am[e][0]), m1 = up2(am[e][1]), m2 = up2(am[e][2]);
        float4 v0 = make_float4(s0[e] * sc, m0.x * sc, m0.y * sc, m1.x * sc);
        float4 v1 = make_float4(m1.y * sc, m2.x * sc, m2.y * sc, s7[e] * sc);
        float* o = out + ob + (size_t)(2 * e + 1) * H_ * W_;
        *reinterpret_cast<float4*>(o)     = v0;
        *reinterpret_cast<float4*>(o + 4) = v1;
    }
}

extern "C" void kernel_launch(void* const* d_in, const int* in_sizes, int n_in,
                              void* d_out, int out_size)
{
    const float* in1 = (const float*)d_in[0];
    const float* in2 = (const float*)d_in[1];
    float* out = (float*)d_out;

    // grid: (y-tile of 2 rows, batch); y fastest -> adjacent blocks share
    // 10 of 12 b rows in L2. 18 warps per block share a/b rows through L1.
    dim3 grid(H_ / 2, B_);
    corr_kernel<<<grid, 576>>>(in1, in2, out);
}

// round 17
// speedup vs baseline: 1.7533x; 1.7533x over previous
#include <cuda_runtime.h>
#include <cstdint>

// FlowNetC correlation cost volume. Inputs [B=8, C=128, H=128, W=256] fp32.
// out[b, (dy+4)*9+(dx+4), y, x] = (1/128) * sum_c in1[b,c,y,x] * in2z[b,c,y+dy,x+dx]
// (in2z zero outside [0,H)x[0,W); PAD=4 >= max displacement 4.)
//
// R16: NO shared memory, DENSE LDG windows, dy-inside-block.
// Block = 9 warps (288 thr) <-> (y, xhalf, b); warp w handles dy = w-4.
// Thread owns 4 adjacent cols x = xbase + 4*lane. Its 12-float b window is
// exactly three DENSE LDG.128s (quads at x-4, x, x+4; 16B lane stride -> 4
// full 128B lines per request, heavy L1 hits between the 3 offset reads).
// All 6 b-pairs are aligned float4 halves -> ZERO packing movs; odd-dx uses
// the single reusable unaligned a-pack (a1,a2) against aligned b-pairs.
// Zero-padding: OOB loads are redirected ONCE (before the channel loop) to a
// device-global zero float4 with per-channel stride 0 -> no in-loop selects.
// The 9 dy-warps share each in1 row through L1 (1 L2 miss + 8 hits).

#define B_  8
#define C_  128
#define H_  128
#define W_  256
#define CHSTRIDE (H_ * W_)          // floats per channel plane

__device__ __align__(16) float g_zero4[4] = {0.f, 0.f, 0.f, 0.f};

__device__ __forceinline__ unsigned long long pk2(float lo, float hi) {
    unsigned long long r;
    asm("mov.b64 %0, {%1, %2};" : "=l"(r) : "f"(lo), "f"(hi));
    return r;
}
__device__ __forceinline__ void fma2(unsigned long long& d,
                                     unsigned long long a, unsigned long long b) {
    asm("fma.rn.f32x2 %0, %1, %2, %0;" : "+l"(d) : "l"(a), "l"(b));
}
__device__ __forceinline__ float2 up2(unsigned long long v) {
    float2 r;
    asm("mov.b64 {%0, %1}, %2;" : "=f"(r.x), "=f"(r.y) : "l"(v));
    return r;
}

__global__ __launch_bounds__(288, 2)
void corr_kernel(const float* __restrict__ in1,
                 const float* __restrict__ in2,
                 float* __restrict__ out)
{
    const int y     = (int)blockIdx.x;            // output row
    const int xh    = (int)blockIdx.y;            // 128-col half
    const int b     = (int)blockIdx.z;
    const int xbase = xh << 7;
    const int w     = (int)threadIdx.x >> 5;      // warp id -> dy = w-4
    const int lane  = (int)threadIdx.x & 31;
    const int dy    = w - 4;
    const int gy    = y + dy;
    const bool rowok = (unsigned)gy < (unsigned)H_;
    const int x     = xbase + (lane << 2);        // first owned col

    // a: 4 floats at cols x..x+3 (always in-bounds); shared by all 9 warps.
    const float* ap = in1 + ((size_t)b * C_ * H_ + y) * W_ + x;

    // b window quads at cols x-4, x, x+4. OOB (or OOB row) -> zero buffer
    // with stride 0; predicates are channel-invariant, resolved ONCE here.
    const float* brow = in2 + ((size_t)b * C_ * H_ + (rowok ? gy : 0)) * W_;
    const bool pL = rowok && (x > 0);             // cols x-4..x-1 valid
    const bool pQ = rowok;
    const bool pR = rowok && (x < 249);           // cols x+4..x+7 valid
    const float* bl = pL ? (brow + x - 4) : g_zero4;
    const float* bq = pQ ? (brow + x)     : g_zero4;
    const float* br = pR ? (brow + x + 4) : g_zero4;
    const size_t sL = pL ? (size_t)CHSTRIDE : 0;
    const size_t sQ = pQ ? (size_t)CHSTRIDE : 0;
    const size_t sR = pR ? (size_t)CHSTRIDE : 0;

    // Accumulators: even d=2e -> 2 f32x2 (cols 01, 23); odd d=2e+1 ->
    // 1 f32x2 (cols 12) + scalars (cols 0, 3). 36 fp32 total.
    unsigned long long ae[5][2], am[4];
    float s0[4], s3[4];
#pragma unroll
    for (int e = 0; e < 5; ++e) { ae[e][0] = 0ull; ae[e][1] = 0ull; }
#pragma unroll
    for (int e = 0; e < 4; ++e) { am[e] = 0ull; s0[e] = 0.0f; s3[e] = 0.0f; }

#pragma unroll 4
    for (int c = 0; c < C_; ++c) {
        float4 a  = *reinterpret_cast<const float4*>(ap);
        float4 wl = *reinterpret_cast<const float4*>(bl);
        float4 wq = *reinterpret_cast<const float4*>(bq);
        float4 wr = *reinterpret_cast<const float4*>(br);
        ap += CHSTRIDE; bl += sL; bq += sQ; br += sR;

        // w[j] <-> col x-4+j; acc col i needs w[i+d].
        // bp[k] = (w[2k], w[2k+1]) -- aligned halves of float4 loads (free).
        unsigned long long bp0 = pk2(wl.x, wl.y), bp1 = pk2(wl.z, wl.w);
        unsigned long long bp2 = pk2(wq.x, wq.y), bp3 = pk2(wq.z, wq.w);
        unsigned long long bp4 = pk2(wr.x, wr.y), bp5 = pk2(wr.z, wr.w);
        unsigned long long bp[6] = {bp0, bp1, bp2, bp3, bp4, bp5};

        unsigned long long a01 = pk2(a.x, a.y);   // aligned (free)
        unsigned long long a23 = pk2(a.z, a.w);   // aligned (free)
        unsigned long long a12 = pk2(a.y, a.z);   // the ONE unaligned pack

        // even d = 2e: cols(0,1) += (a0,a1)*bp[e]; cols(2,3) += (a2,a3)*bp[e+1]
#pragma unroll
        for (int e = 0; e < 5; ++e) {
            fma2(ae[e][0], a01, bp[e]);
            fma2(ae[e][1], a23, bp[e + 1]);
        }
        // odd d = 2e+1: cols(1,2) += (a1,a2)*bp[e+1] (aligned b-pair);
        // col0 += a0*w[2e+1]; col3 += a3*w[2e+4]
        float wlv[4] = {wl.x, wl.y, wl.z, wl.w};
        float wqv[4] = {wq.x, wq.y, wq.z, wq.w};
        float wrv[4] = {wr.x, wr.y, wr.z, wr.w};
#pragma unroll
        for (int e = 0; e < 4; ++e) {
            fma2(am[e], a12, bp[e + 1]);
            // w[2e+1]: e=0,1 -> wl.y,wl.w ; e=2,3 -> wq.y,wq.w
            float c0 = (e < 2) ? wlv[2 * e + 1] : wqv[2 * (e - 2) + 1];
            // w[2e+4]: e=0,1 -> wq.x,wq.z ; e=2,3 -> wr.x,wr.z
            float c3 = (e < 2) ? wqv[2 * e] : wrv[2 * (e - 2)];
            s0[e] = fmaf(a.x, c0, s0[e]);
            s3[e] = fmaf(a.w, c3, s3[e]);
        }
    }

    // ---- epilogue: scale by 1/C, one float4 store per dx ----
    const float sc = 1.0f / (float)C_;
    const size_t ob = (((size_t)b * 81 + (size_t)(dy + 4) * 9) * H_ + y) * W_ + x;
#pragma unroll
    for (int e = 0; e < 5; ++e) {                 // d = 2e
        float2 lo = up2(ae[e][0]), hi = up2(ae[e][1]);
        float4 v = make_float4(lo.x * sc, lo.y * sc, hi.x * sc, hi.y * sc);
        *reinterpret_cast<float4*>(out + ob + (size_t)(2 * e) * H_ * W_) = v;
    }
#pragma unroll
    for (int e = 0; e < 4; ++e) {                 // d = 2e+1
        float2 m = up2(am[e]);
        float4 v = make_float4(s0[e] * sc, m.x * sc, m.y * sc, s3[e] * sc);
        *reinterpret_cast<float4*>(out + ob + (size_t)(2 * e + 1) * H_ * W_) = v;
    }
}

extern "C" void kernel_launch(void* const* d_in, const int* in_sizes, int n_in,
                              void* d_out, int out_size)
{
    const float* in1 = (const float*)d_in[0];
    const float* in2 = (const float*)d_in[1];
    float* out = (float*)d_out;

    // (y, xhalf, b): 9 dy-warps per block share the in1 row through L1;
    // y fastest -> adjacent blocks overlap 8/9 of their in2 rows in L2.
    dim3 grid(H_, 2, B_);
    corr_kernel<<<grid, 288>>>(in1, in2, out);
}